// round 5
// baseline (speedup 1.0000x reference)
#include <cuda_runtime.h>
#include <cuda_bf16.h>
#include <cstdint>

#define BATCH  16384
#define DIM    128
#define NEDGES 500000
#define EPSL   1e-6f
#define PITCH  136   // bf16 elems per smem row (272 B = 17*16B -> conflict-free)
#define L2E    1.4426950408889634f
#define L2E2   (1.4426950408889634f * 1.4426950408889634f)

// ---------------- device scratch ------------------------------------------------
__device__ float          g_ns[BATCH];          // L2E^2 * ||ps_row||^2
__device__ float          g_nq[BATCH];          // L2E^2 * ||pp_row||^2
__device__ float          g_bps[BATCH];         // L2E * beta_p_star[nodes_p_star]
__device__ float          g_bp[BATCH];          // L2E * beta_p[nodes_p]
__device__ __nv_bfloat16  g_psh[BATCH * DIM];   // L2E-scaled bf16 p_star rows
__device__ __nv_bfloat16  g_pph[BATCH * DIM];   // L2E-scaled bf16 p rows
__device__ double         g_acc[2];             // [0]=link, [1]=non_link

// ---------------- gather (+ zero accumulators) ----------------------------------
__global__ void gather_kernel(const int* __restrict__ nodes_p_star,
                              const int* __restrict__ nodes_p,
                              const float* __restrict__ beta_p,
                              const float* __restrict__ beta_p_star,
                              const float* __restrict__ p,
                              const float* __restrict__ p_star) {
    if (blockIdx.x == 0 && threadIdx.x == 0) { g_acc[0] = 0.0; g_acc[1] = 0.0; }
    int gw   = (blockIdx.x * blockDim.x + threadIdx.x) >> 5;
    int lane = threadIdx.x & 31;
    if (gw >= 2 * BATCH) return;
    bool is_ps = (gw < BATCH);
    int r   = is_ps ? gw : gw - BATCH;
    int idx = is_ps ? nodes_p_star[r] : nodes_p[r];
    const float4* src = (const float4*)((is_ps ? p_star : p) + (size_t)idx * DIM);
    __nv_bfloat162* dsth = (__nv_bfloat162*)((is_ps ? g_psh : g_pph) + (size_t)r * DIM);
    float nrm = 0.f;
#pragma unroll
    for (int c = lane; c < DIM / 4; c += 32) {
        float4 v = src[c];
        nrm += v.x * v.x + v.y * v.y + v.z * v.z + v.w * v.w;
        dsth[2 * c]     = __floats2bfloat162_rn(v.x * L2E, v.y * L2E);
        dsth[2 * c + 1] = __floats2bfloat162_rn(v.z * L2E, v.w * L2E);
    }
#pragma unroll
    for (int o = 16; o; o >>= 1) nrm += __shfl_xor_sync(0xffffffffu, nrm, o);
    if (lane == 0) {
        if (is_ps) { g_ns[r] = nrm * L2E2; g_bps[r] = beta_p_star[idx] * L2E; }
        else       { g_nq[r] = nrm * L2E2; g_bp[r]  = beta_p[idx] * L2E; }
    }
}

// ---------------- link term: one warp per edge ----------------------------------
__global__ void link_kernel(const int* __restrict__ edges,
                            const float* __restrict__ beta_p,
                            const float* __restrict__ beta_p_star,
                            const float* __restrict__ p,
                            const float* __restrict__ p_star) {
    int gw   = (blockIdx.x * blockDim.x + threadIdx.x) >> 5;
    int lane = threadIdx.x & 31;
    int wid  = threadIdx.x >> 5;
    float contrib = 0.f;
    if (gw < NEDGES) {
        int i0 = edges[gw];
        int i1 = edges[NEDGES + gw];
        float4 av = ((const float4*)(p      + (size_t)i0 * DIM))[lane];
        float4 bv = ((const float4*)(p_star + (size_t)i1 * DIM))[lane];
        float dx = av.x - bv.x + EPSL;
        float dy = av.y - bv.y + EPSL;
        float dz = av.z - bv.z + EPSL;
        float dw = av.w - bv.w + EPSL;
        float s = dx * dx + dy * dy + dz * dz + dw * dw;
#pragma unroll
        for (int o = 16; o; o >>= 1) s += __shfl_xor_sync(0xffffffffu, s, o);
        if (lane == 0)
            contrib = beta_p_star[i0] + beta_p[i1] - sqrtf(s);
    }
    __shared__ double red[8];
    if (lane == 0) red[wid] = (double)contrib;
    __syncthreads();
    if (threadIdx.x == 0) {
        double t = 0.0;
#pragma unroll
        for (int w = 0; w < 8; w++) t += red[w];
        atomicAdd(&g_acc[0], t);
    }
}

// ---------------- MMA helpers ---------------------------------------------------
__device__ __forceinline__ void ldsm_x4(uint32_t& r0, uint32_t& r1,
                                        uint32_t& r2, uint32_t& r3, const void* p) {
    uint32_t a = (uint32_t)__cvta_generic_to_shared(p);
    asm volatile("ldmatrix.sync.aligned.m8n8.x4.shared.b16 {%0,%1,%2,%3},[%4];"
                 : "=r"(r0), "=r"(r1), "=r"(r2), "=r"(r3) : "r"(a));
}

__device__ __forceinline__ void mma16816(float* c, const uint32_t* a, const uint32_t* b) {
    asm volatile(
        "mma.sync.aligned.m16n8k16.row.col.f32.bf16.bf16.f32 "
        "{%0,%1,%2,%3},{%4,%5,%6,%7},{%8,%9},{%0,%1,%2,%3};"
        : "+f"(c[0]), "+f"(c[1]), "+f"(c[2]), "+f"(c[3])
        : "r"(a[0]), "r"(a[1]), "r"(a[2]), "r"(a[3]), "r"(b[0]), "r"(b[1]));
}

__device__ __forceinline__ float fsqrt_ap(float x) {
    float r; asm("sqrt.approx.f32 %0, %1;" : "=f"(r) : "f"(x)); return r;
}
__device__ __forceinline__ float fex2_ap(float x) {
    float r; asm("ex2.approx.f32 %0, %1;" : "=f"(r) : "f"(x)); return r;
}

// ---------------- non-link: 128x128 bf16 tensor tile, fast-math epilogue --------
__global__ void __launch_bounds__(256, 2) nonlink_kernel() {
    int ts = blockIdx.y, tq = blockIdx.x;
    if (tq < ts) return;

    extern __shared__ __nv_bfloat16 sm[];
    __nv_bfloat16* As = sm;                 // [128][PITCH]
    __nv_bfloat16* Bs = sm + 128 * PITCH;   // [128][PITCH]

    int tid  = threadIdx.x;
    int lane = tid & 31;
    int wid  = tid >> 5;
    int s0 = ts * 128, q0 = tq * 128;

    {
        int chunk = tid & 15;
        int rbase = tid >> 4;
#pragma unroll
        for (int i = 0; i < 8; i++) {
            int row = rbase + 16 * i;
            uint4 va = ((const uint4*)(g_psh + (size_t)(s0 + row) * DIM))[chunk];
            uint4 vb = ((const uint4*)(g_pph + (size_t)(q0 + row) * DIM))[chunk];
            *(uint4*)(As + row * PITCH + chunk * 8) = va;
            *(uint4*)(Bs + row * PITCH + chunk * 8) = vb;
        }
    }
    __syncthreads();

    int wm = wid & 1;
    int wn = wid >> 1;
    int m_base = wm * 64;
    int n_base = wn * 32;

    float acc[4][4][4];
#pragma unroll
    for (int mi = 0; mi < 4; mi++)
#pragma unroll
        for (int nj = 0; nj < 4; nj++)
#pragma unroll
            for (int r = 0; r < 4; r++) acc[mi][nj][r] = 0.f;

    int a_row_off = lane & 15;
    int a_k_off   = 8 * (lane >> 4);
    int b_row_off = ((lane >> 4) << 3) + (lane & 7);
    int b_k_off   = ((lane >> 3) & 1) * 8;

#pragma unroll
    for (int k0 = 0; k0 < DIM; k0 += 16) {
        uint32_t a[4][4];
#pragma unroll
        for (int mi = 0; mi < 4; mi++) {
            const __nv_bfloat16* pa =
                As + (m_base + mi * 16 + a_row_off) * PITCH + k0 + a_k_off;
            ldsm_x4(a[mi][0], a[mi][1], a[mi][2], a[mi][3], pa);
        }
        uint32_t b[4][2];
#pragma unroll
        for (int pr = 0; pr < 2; pr++) {
            const __nv_bfloat16* pb =
                Bs + (n_base + pr * 16 + b_row_off) * PITCH + k0 + b_k_off;
            uint32_t r0, r1, r2, r3;
            ldsm_x4(r0, r1, r2, r3, pb);
            b[pr * 2][0] = r0; b[pr * 2][1] = r1;
            b[pr * 2 + 1][0] = r2; b[pr * 2 + 1][1] = r3;
        }
#pragma unroll
        for (int mi = 0; mi < 4; mi++)
#pragma unroll
            for (int nj = 0; nj < 4; nj++)
                mma16816(acc[mi][nj], a[mi], b[nj]);
    }

    // ---------- fused epilogue (ex2-folded, approx MUFU) ----------
    int g = lane >> 2, t = lane & 3;
    float nsv[8], bpsv[8];
#pragma unroll
    for (int mi = 0; mi < 4; mi++) {
        int r = s0 + m_base + mi * 16 + g;
        nsv[2 * mi]      = g_ns[r];      nsv[2 * mi + 1]  = g_ns[r + 8];
        bpsv[2 * mi]     = g_bps[r];     bpsv[2 * mi + 1] = g_bps[r + 8];
    }
    float nqv[8], bpv[8];
#pragma unroll
    for (int nj = 0; nj < 4; nj++) {
        int c = q0 + n_base + nj * 8 + 2 * t;
        nqv[2 * nj]      = g_nq[c];      nqv[2 * nj + 1] = g_nq[c + 1];
        bpv[2 * nj]      = g_bp[c];      bpv[2 * nj + 1] = g_bp[c + 1];
    }

    float lsum0 = 0.f, lsum1 = 0.f;
    if (ts != tq) {
#pragma unroll
        for (int mi = 0; mi < 4; mi++) {
#pragma unroll
            for (int nj = 0; nj < 4; nj++) {
#pragma unroll
                for (int rr = 0; rr < 4; rr++) {
                    float ns = nsv[2 * mi + (rr >> 1)];
                    float bs = bpsv[2 * mi + (rr >> 1)];
                    float nq = nqv[2 * nj + (rr & 1)];
                    float bq = bpv[2 * nj + (rr & 1)];
                    float sq = fmaxf(ns + fmaf(-2.f, acc[mi][nj][rr], nq), 0.f);
                    float e  = fex2_ap((bs + bq) - fsqrt_ap(sq));
                    if (rr & 1) lsum1 += e; else lsum0 += e;
                }
            }
        }
    } else {
#pragma unroll
        for (int mi = 0; mi < 4; mi++) {
            int rloc0 = m_base + mi * 16 + g;
#pragma unroll
            for (int nj = 0; nj < 4; nj++) {
                int cloc0 = n_base + nj * 8 + 2 * t;
#pragma unroll
                for (int rr = 0; rr < 4; rr++) {
                    int rloc = rloc0 + (rr >> 1) * 8;
                    int cloc = cloc0 + (rr & 1);
                    float ns = nsv[2 * mi + (rr >> 1)];
                    float bs = bpsv[2 * mi + (rr >> 1)];
                    float nq = nqv[2 * nj + (rr & 1)];
                    float bq = bpv[2 * nj + (rr & 1)];
                    float sq = fmaxf(ns + fmaf(-2.f, acc[mi][nj][rr], nq), 0.f);
                    float e  = fex2_ap((bs + bq) - fsqrt_ap(sq));
                    if (cloc > rloc) { if (rr & 1) lsum1 += e; else lsum0 += e; }
                }
            }
        }
    }

    float lsum = lsum0 + lsum1;
#pragma unroll
    for (int o = 16; o; o >>= 1) lsum += __shfl_xor_sync(0xffffffffu, lsum, o);
    __shared__ double red[8];
    if (lane == 0) red[wid] = (double)lsum;
    __syncthreads();
    if (tid == 0) {
        double s = 0.0;
#pragma unroll
        for (int w = 0; w < 8; w++) s += red[w];
        atomicAdd(&g_acc[1], s);
    }
}

// ---------------- finalize ------------------------------------------------------
__global__ void finalize_kernel(float* out) {
    if (threadIdx.x == 0)
        out[0] = (float)(g_acc[1] - g_acc[0]);  // -(link - nonlink)
}

// ---------------- launch --------------------------------------------------------
extern "C" void kernel_launch(void* const* d_in, const int* in_sizes, int n_in,
                              void* d_out, int out_size) {
    const int*   edges        = (const int*)d_in[0];
    const int*   nodes_p_star = (const int*)d_in[1];
    const int*   nodes_p      = (const int*)d_in[2];
    const float* beta_p       = (const float*)d_in[3];
    const float* beta_p_star  = (const float*)d_in[4];
    const float* p            = (const float*)d_in[5];
    const float* p_star       = (const float*)d_in[6];
    float* out = (float*)d_out;

    static const size_t NL_SMEM = 2 * 128 * PITCH * sizeof(__nv_bfloat16); // 69632 B
    cudaFuncSetAttribute(nonlink_kernel,
                         cudaFuncAttributeMaxDynamicSharedMemorySize, (int)NL_SMEM);

    gather_kernel<<<(2 * BATCH) / 8, 256>>>(nodes_p_star, nodes_p,
                                            beta_p, beta_p_star, p, p_star);

    link_kernel<<<(NEDGES + 7) / 8, 256>>>(edges, beta_p, beta_p_star, p, p_star);

    dim3 grid(BATCH / 128, BATCH / 128);
    nonlink_kernel<<<grid, 256, NL_SMEM>>>();

    finalize_kernel<<<1, 32>>>(out);
}

// round 6
// speedup vs baseline: 1.3390x; 1.3390x over previous
#include <cuda_runtime.h>
#include <cuda_bf16.h>
#include <cstdint>

#define BATCH  16384
#define DIM    128
#define NEDGES 500000
#define EPSL   1e-6f
#define PITCH  136   // bf16 elems per smem row (272 B = 17*16B -> conflict-free)
#define NTILE  128
#define NT     (NTILE * (NTILE + 1) / 2)   // 8256 triangular tiles
#define L2E    1.4426950408889634f
#define L2E2   (1.4426950408889634f * 1.4426950408889634f)

// ---------------- device scratch ------------------------------------------------
__device__ float          g_ns[BATCH];          // L2E^2 * ||ps_row||^2
__device__ float          g_nq[BATCH];          // L2E^2 * ||pp_row||^2
__device__ float          g_bps[BATCH];         // L2E * beta_p_star[nodes_p_star]
__device__ float          g_bp[BATCH];          // L2E * beta_p[nodes_p]
__device__ __nv_bfloat16  g_psh[BATCH * DIM];   // L2E-scaled bf16 p_star rows
__device__ __nv_bfloat16  g_pph[BATCH * DIM];   // L2E-scaled bf16 p rows
__device__ double         g_acc[2];             // [0]=link, [1]=non_link
__device__ unsigned int   g_done;               // completion counter (self-resetting)

// ---------------- gather (+ zero accumulators) ----------------------------------
__global__ void gather_kernel(const int* __restrict__ nodes_p_star,
                              const int* __restrict__ nodes_p,
                              const float* __restrict__ beta_p,
                              const float* __restrict__ beta_p_star,
                              const float* __restrict__ p,
                              const float* __restrict__ p_star) {
    if (blockIdx.x == 0 && threadIdx.x == 0) { g_acc[0] = 0.0; g_acc[1] = 0.0; }
    int gw   = (blockIdx.x * blockDim.x + threadIdx.x) >> 5;
    int lane = threadIdx.x & 31;
    if (gw >= 2 * BATCH) return;
    bool is_ps = (gw < BATCH);
    int r   = is_ps ? gw : gw - BATCH;
    int idx = is_ps ? nodes_p_star[r] : nodes_p[r];
    const float4* src = (const float4*)((is_ps ? p_star : p) + (size_t)idx * DIM);
    __nv_bfloat162* dsth = (__nv_bfloat162*)((is_ps ? g_psh : g_pph) + (size_t)r * DIM);
    float nrm = 0.f;
#pragma unroll
    for (int c = lane; c < DIM / 4; c += 32) {
        float4 v = src[c];
        nrm += v.x * v.x + v.y * v.y + v.z * v.z + v.w * v.w;
        dsth[2 * c]     = __floats2bfloat162_rn(v.x * L2E, v.y * L2E);
        dsth[2 * c + 1] = __floats2bfloat162_rn(v.z * L2E, v.w * L2E);
    }
#pragma unroll
    for (int o = 16; o; o >>= 1) nrm += __shfl_xor_sync(0xffffffffu, nrm, o);
    if (lane == 0) {
        if (is_ps) { g_ns[r] = nrm * L2E2; g_bps[r] = beta_p_star[idx] * L2E; }
        else       { g_nq[r] = nrm * L2E2; g_bp[r]  = beta_p[idx] * L2E; }
    }
}

// ---------------- MMA helpers ---------------------------------------------------
__device__ __forceinline__ void ldsm_x4(uint32_t& r0, uint32_t& r1,
                                        uint32_t& r2, uint32_t& r3, const void* p) {
    uint32_t a = (uint32_t)__cvta_generic_to_shared(p);
    asm volatile("ldmatrix.sync.aligned.m8n8.x4.shared.b16 {%0,%1,%2,%3},[%4];"
                 : "=r"(r0), "=r"(r1), "=r"(r2), "=r"(r3) : "r"(a));
}

__device__ __forceinline__ void mma16816(float* c, const uint32_t* a, const uint32_t* b) {
    asm volatile(
        "mma.sync.aligned.m16n8k16.row.col.f32.bf16.bf16.f32 "
        "{%0,%1,%2,%3},{%4,%5,%6,%7},{%8,%9},{%0,%1,%2,%3};"
        : "+f"(c[0]), "+f"(c[1]), "+f"(c[2]), "+f"(c[3])
        : "r"(a[0]), "r"(a[1]), "r"(a[2]), "r"(a[3]), "r"(b[0]), "r"(b[1]));
}

__device__ __forceinline__ float fsqrt_ap(float x) {
    float r; asm("sqrt.approx.f32 %0, %1;" : "=f"(r) : "f"(x)); return r;
}
__device__ __forceinline__ float fex2_ap(float x) {
    float r; asm("ex2.approx.f32 %0, %1;" : "=f"(r) : "f"(x)); return r;
}

// ---------------- fused: link prologue + nonlink tile + last-block finalize -----
__global__ void __launch_bounds__(256, 2) fused_kernel(
        const int* __restrict__ edges,
        const float* __restrict__ beta_p,
        const float* __restrict__ beta_p_star,
        const float* __restrict__ p,
        const float* __restrict__ p_star,
        float* __restrict__ out) {
    extern __shared__ __nv_bfloat16 sm[];
    __nv_bfloat16* As = sm;                 // [128][PITCH]
    __nv_bfloat16* Bs = sm + 128 * PITCH;   // [128][PITCH]
    __shared__ double sredl[8];             // link reduction
    __shared__ double sredn[8];             // nonlink reduction

    int bid  = blockIdx.x;
    int tid  = threadIdx.x;
    int lane = tid & 31;
    int wid  = tid >> 5;

    // ===== link prologue: grid-strided edges, one warp per edge =====
    {
        float wacc = 0.f;
        for (int e = bid * 8 + wid; e < NEDGES; e += NT * 8) {
            int i0 = edges[e];
            int i1 = edges[NEDGES + e];
            float4 av = ((const float4*)(p      + (size_t)i0 * DIM))[lane];
            float4 bv = ((const float4*)(p_star + (size_t)i1 * DIM))[lane];
            float dx = av.x - bv.x + EPSL;
            float dy = av.y - bv.y + EPSL;
            float dz = av.z - bv.z + EPSL;
            float dw = av.w - bv.w + EPSL;
            float s = dx * dx + dy * dy + dz * dz + dw * dw;
#pragma unroll
            for (int o = 16; o; o >>= 1) s += __shfl_xor_sync(0xffffffffu, s, o);
            if (lane == 0)
                wacc += beta_p_star[i0] + beta_p[i1] - fsqrt_ap(s);
        }
        if (lane == 0) sredl[wid] = (double)wacc;
    }

    // ===== tile decode (column-major triangular: t = tq*(tq+1)/2 + ts) =====
    int t = bid;
    int tq = (int)((fsqrt_ap(8.f * (float)t + 1.f) - 1.f) * 0.5f);
    while ((tq + 1) * (tq + 2) / 2 <= t) tq++;
    while (tq * (tq + 1) / 2 > t) tq--;
    int ts = t - tq * (tq + 1) / 2;
    int s0 = ts * 128, q0 = tq * 128;

    // ===== smem fill =====
    {
        int chunk = tid & 15;
        int rbase = tid >> 4;
#pragma unroll
        for (int i = 0; i < 8; i++) {
            int row = rbase + 16 * i;
            uint4 va = ((const uint4*)(g_psh + (size_t)(s0 + row) * DIM))[chunk];
            uint4 vb = ((const uint4*)(g_pph + (size_t)(q0 + row) * DIM))[chunk];
            *(uint4*)(As + row * PITCH + chunk * 8) = va;
            *(uint4*)(Bs + row * PITCH + chunk * 8) = vb;
        }
    }
    __syncthreads();

    // link block-level reduce (overlaps others' mainloop)
    if (tid == 0) {
        double tl = 0.0;
#pragma unroll
        for (int w = 0; w < 8; w++) tl += sredl[w];
        atomicAdd(&g_acc[0], tl);
    }

    // ===== MMA mainloop =====
    int wm = wid & 1;
    int wn = wid >> 1;
    int m_base = wm * 64;
    int n_base = wn * 32;

    float acc[4][4][4];
#pragma unroll
    for (int mi = 0; mi < 4; mi++)
#pragma unroll
        for (int nj = 0; nj < 4; nj++)
#pragma unroll
            for (int r = 0; r < 4; r++) acc[mi][nj][r] = 0.f;

    int a_row_off = lane & 15;
    int a_k_off   = 8 * (lane >> 4);
    int b_row_off = ((lane >> 4) << 3) + (lane & 7);
    int b_k_off   = ((lane >> 3) & 1) * 8;

#pragma unroll
    for (int k0 = 0; k0 < DIM; k0 += 16) {
        uint32_t a[4][4];
#pragma unroll
        for (int mi = 0; mi < 4; mi++) {
            const __nv_bfloat16* pa =
                As + (m_base + mi * 16 + a_row_off) * PITCH + k0 + a_k_off;
            ldsm_x4(a[mi][0], a[mi][1], a[mi][2], a[mi][3], pa);
        }
        uint32_t b[4][2];
#pragma unroll
        for (int pr = 0; pr < 2; pr++) {
            const __nv_bfloat16* pb =
                Bs + (n_base + pr * 16 + b_row_off) * PITCH + k0 + b_k_off;
            uint32_t r0, r1, r2, r3;
            ldsm_x4(r0, r1, r2, r3, pb);
            b[pr * 2][0] = r0; b[pr * 2][1] = r1;
            b[pr * 2 + 1][0] = r2; b[pr * 2 + 1][1] = r3;
        }
#pragma unroll
        for (int mi = 0; mi < 4; mi++)
#pragma unroll
            for (int nj = 0; nj < 4; nj++)
                mma16816(acc[mi][nj], a[mi], b[nj]);
    }

    // ===== fused epilogue (ex2-folded, approx MUFU) =====
    int g = lane >> 2, tt = lane & 3;
    float nsv[8], bpsv[8];
#pragma unroll
    for (int mi = 0; mi < 4; mi++) {
        int r = s0 + m_base + mi * 16 + g;
        nsv[2 * mi]      = g_ns[r];      nsv[2 * mi + 1]  = g_ns[r + 8];
        bpsv[2 * mi]     = g_bps[r];     bpsv[2 * mi + 1] = g_bps[r + 8];
    }
    float nqv[8], bpv[8];
#pragma unroll
    for (int nj = 0; nj < 4; nj++) {
        int c = q0 + n_base + nj * 8 + 2 * tt;
        nqv[2 * nj]      = g_nq[c];      nqv[2 * nj + 1] = g_nq[c + 1];
        bpv[2 * nj]      = g_bp[c];      bpv[2 * nj + 1] = g_bp[c + 1];
    }

    float lsum0 = 0.f, lsum1 = 0.f;
    if (ts != tq) {
#pragma unroll
        for (int mi = 0; mi < 4; mi++) {
#pragma unroll
            for (int nj = 0; nj < 4; nj++) {
#pragma unroll
                for (int rr = 0; rr < 4; rr++) {
                    float ns = nsv[2 * mi + (rr >> 1)];
                    float bs = bpsv[2 * mi + (rr >> 1)];
                    float nq = nqv[2 * nj + (rr & 1)];
                    float bq = bpv[2 * nj + (rr & 1)];
                    float sq = fmaxf(ns + fmaf(-2.f, acc[mi][nj][rr], nq), 0.f);
                    float e  = fex2_ap((bs + bq) - fsqrt_ap(sq));
                    if (rr & 1) lsum1 += e; else lsum0 += e;
                }
            }
        }
    } else {
#pragma unroll
        for (int mi = 0; mi < 4; mi++) {
            int rloc0 = m_base + mi * 16 + g;
#pragma unroll
            for (int nj = 0; nj < 4; nj++) {
                int cloc0 = n_base + nj * 8 + 2 * tt;
#pragma unroll
                for (int rr = 0; rr < 4; rr++) {
                    int rloc = rloc0 + (rr >> 1) * 8;
                    int cloc = cloc0 + (rr & 1);
                    float ns = nsv[2 * mi + (rr >> 1)];
                    float bs = bpsv[2 * mi + (rr >> 1)];
                    float nq = nqv[2 * nj + (rr & 1)];
                    float bq = bpv[2 * nj + (rr & 1)];
                    float sq = fmaxf(ns + fmaf(-2.f, acc[mi][nj][rr], nq), 0.f);
                    float e  = fex2_ap((bs + bq) - fsqrt_ap(sq));
                    if (cloc > rloc) { if (rr & 1) lsum1 += e; else lsum0 += e; }
                }
            }
        }
    }

    float lsum = lsum0 + lsum1;
#pragma unroll
    for (int o = 16; o; o >>= 1) lsum += __shfl_xor_sync(0xffffffffu, lsum, o);
    if (lane == 0) sredn[wid] = (double)lsum;
    __syncthreads();
    if (tid == 0) {
        double s = 0.0;
#pragma unroll
        for (int w = 0; w < 8; w++) s += sredn[w];
        atomicAdd(&g_acc[1], s);
        // ---- last block finalizes ----
        __threadfence();
        unsigned int done = atomicAdd(&g_done, 1u);
        if (done == NT - 1) {
            g_done = 0u;                                  // self-reset for next replay
            out[0] = (float)(g_acc[1] - g_acc[0]);        // -(link - nonlink)
        }
    }
}

// ---------------- launch --------------------------------------------------------
extern "C" void kernel_launch(void* const* d_in, const int* in_sizes, int n_in,
                              void* d_out, int out_size) {
    const int*   edges        = (const int*)d_in[0];
    const int*   nodes_p_star = (const int*)d_in[1];
    const int*   nodes_p      = (const int*)d_in[2];
    const float* beta_p       = (const float*)d_in[3];
    const float* beta_p_star  = (const float*)d_in[4];
    const float* p            = (const float*)d_in[5];
    const float* p_star       = (const float*)d_in[6];
    float* out = (float*)d_out;

    static const size_t NL_SMEM = 2 * 128 * PITCH * sizeof(__nv_bfloat16); // 69632 B
    cudaFuncSetAttribute(fused_kernel,
                         cudaFuncAttributeMaxDynamicSharedMemorySize, (int)NL_SMEM);

    gather_kernel<<<(2 * BATCH) / 8, 256>>>(nodes_p_star, nodes_p,
                                            beta_p, beta_p_star, p, p_star);

    fused_kernel<<<NT, 256, NL_SMEM>>>(edges, beta_p, beta_p_star, p, p_star, out);
}

// round 7
// speedup vs baseline: 1.4991x; 1.1196x over previous
#include <cuda_runtime.h>
#include <cuda_bf16.h>
#include <cstdint>

#define BATCH  16384
#define DIM    128
#define NEDGES 500000
#define EPSL   1e-6f
#define PITCH  136   // bf16 elems per smem row (272 B) -> ldmatrix conflict-free
#define NT2    16512 // number of (128s x 64q) tiles kept
#define L2E    1.4426950408889634f
#define L2E2   (1.4426950408889634f * 1.4426950408889634f)

// ---------------- device scratch ------------------------------------------------
__device__ float          g_ns[BATCH];
__device__ float          g_nq[BATCH];
__device__ float          g_bps[BATCH];
__device__ float          g_bp[BATCH];
__device__ __nv_bfloat16  g_psh[BATCH * DIM];
__device__ __nv_bfloat16  g_pph[BATCH * DIM];
__device__ double         g_acc[2];             // [0]=link, [1]=non_link
__device__ unsigned int   g_done;

// ---------------- gather (+ zero accumulators) ----------------------------------
__global__ void gather_kernel(const int* __restrict__ nodes_p_star,
                              const int* __restrict__ nodes_p,
                              const float* __restrict__ beta_p,
                              const float* __restrict__ beta_p_star,
                              const float* __restrict__ p,
                              const float* __restrict__ p_star) {
    if (blockIdx.x == 0 && threadIdx.x == 0) { g_acc[0] = 0.0; g_acc[1] = 0.0; }
    int gw   = (blockIdx.x * blockDim.x + threadIdx.x) >> 5;
    int lane = threadIdx.x & 31;
    if (gw >= 2 * BATCH) return;
    bool is_ps = (gw < BATCH);
    int r   = is_ps ? gw : gw - BATCH;
    int idx = is_ps ? nodes_p_star[r] : nodes_p[r];
    const float4* src = (const float4*)((is_ps ? p_star : p) + (size_t)idx * DIM);
    __nv_bfloat162* dsth = (__nv_bfloat162*)((is_ps ? g_psh : g_pph) + (size_t)r * DIM);
    float nrm = 0.f;
#pragma unroll
    for (int c = lane; c < DIM / 4; c += 32) {
        float4 v = src[c];
        nrm += v.x * v.x + v.y * v.y + v.z * v.z + v.w * v.w;
        dsth[2 * c]     = __floats2bfloat162_rn(v.x * L2E, v.y * L2E);
        dsth[2 * c + 1] = __floats2bfloat162_rn(v.z * L2E, v.w * L2E);
    }
#pragma unroll
    for (int o = 16; o; o >>= 1) nrm += __shfl_xor_sync(0xffffffffu, nrm, o);
    if (lane == 0) {
        if (is_ps) { g_ns[r] = nrm * L2E2; g_bps[r] = beta_p_star[idx] * L2E; }
        else       { g_nq[r] = nrm * L2E2; g_bp[r]  = beta_p[idx] * L2E; }
    }
}

// ---------------- helpers -------------------------------------------------------
__device__ __forceinline__ void ldsm_x4(uint32_t& r0, uint32_t& r1,
                                        uint32_t& r2, uint32_t& r3, const void* p) {
    uint32_t a = (uint32_t)__cvta_generic_to_shared(p);
    asm volatile("ldmatrix.sync.aligned.m8n8.x4.shared.b16 {%0,%1,%2,%3},[%4];"
                 : "=r"(r0), "=r"(r1), "=r"(r2), "=r"(r3) : "r"(a));
}
__device__ __forceinline__ void mma16816(float* c, const uint32_t* a, const uint32_t* b) {
    asm volatile(
        "mma.sync.aligned.m16n8k16.row.col.f32.bf16.bf16.f32 "
        "{%0,%1,%2,%3},{%4,%5,%6,%7},{%8,%9},{%0,%1,%2,%3};"
        : "+f"(c[0]), "+f"(c[1]), "+f"(c[2]), "+f"(c[3])
        : "r"(a[0]), "r"(a[1]), "r"(a[2]), "r"(a[3]), "r"(b[0]), "r"(b[1]));
}
__device__ __forceinline__ float fsqrt_ap(float x) {
    float r; asm("sqrt.approx.f32 %0, %1;" : "=f"(r) : "f"(x)); return r;
}
__device__ __forceinline__ float fex2_ap(float x) {
    float r; asm("ex2.approx.f32 %0, %1;" : "=f"(r) : "f"(x)); return r;
}

// ---------------- fused: link prologue + 128x64 tile + last-block finalize ------
// Tile set: for s-tile ts (128 rows), q-tiles tq2 (64 cols) with tq2 >= 2*ts.
// cum(ts) = ts*(257-ts); tiles at offset<2 straddle the diagonal -> masked.
__global__ void __launch_bounds__(256, 3) fused_kernel(
        const int* __restrict__ edges,
        const float* __restrict__ beta_p,
        const float* __restrict__ beta_p_star,
        const float* __restrict__ p,
        const float* __restrict__ p_star,
        float* __restrict__ out) {
    extern __shared__ __nv_bfloat16 sm[];
    __nv_bfloat16* As = sm;                // [128][PITCH]
    __nv_bfloat16* Bs = sm + 128 * PITCH;  // [64][PITCH]
    __shared__ double sredl[8];
    __shared__ double sredn[8];

    int bid  = blockIdx.x;
    int tid  = threadIdx.x;
    int lane = tid & 31;
    int wid  = tid >> 5;

    // ===== link prologue: grid-strided edges, one warp per edge =====
    {
        float wacc = 0.f;
        for (int e = bid * 8 + wid; e < NEDGES; e += NT2 * 8) {
            int i0 = edges[e];
            int i1 = edges[NEDGES + e];
            float4 av = ((const float4*)(p      + (size_t)i0 * DIM))[lane];
            float4 bv = ((const float4*)(p_star + (size_t)i1 * DIM))[lane];
            float dx = av.x - bv.x + EPSL;
            float dy = av.y - bv.y + EPSL;
            float dz = av.z - bv.z + EPSL;
            float dw = av.w - bv.w + EPSL;
            float s = dx * dx + dy * dy + dz * dz + dw * dw;
#pragma unroll
            for (int o = 16; o; o >>= 1) s += __shfl_xor_sync(0xffffffffu, s, o);
            if (lane == 0)
                wacc += beta_p_star[i0] + beta_p[i1] - fsqrt_ap(s);
        }
        if (lane == 0) sredl[wid] = (double)wacc;
    }

    // ===== tile decode =====
    int t  = bid;
    int ts = (int)((257.f - fsqrt_ap(66049.f - 4.f * (float)t)) * 0.5f);
    while (ts > 0 && ts * (257 - ts) > t) ts--;
    while ((ts + 1) * (257 - (ts + 1)) <= t) ts++;
    int off = t - ts * (257 - ts);
    int tq2 = 2 * ts + off;
    int s0 = ts * 128, q0 = tq2 * 64;
    bool masked = (off < 2);

    // ===== smem fill =====
    {
        int chunk = tid & 15;
        int rbase = tid >> 4;
#pragma unroll
        for (int i = 0; i < 8; i++) {
            int row = rbase + 16 * i;
            uint4 va = ((const uint4*)(g_psh + (size_t)(s0 + row) * DIM))[chunk];
            *(uint4*)(As + row * PITCH + chunk * 8) = va;
        }
#pragma unroll
        for (int i = 0; i < 4; i++) {
            int row = rbase + 16 * i;
            uint4 vb = ((const uint4*)(g_pph + (size_t)(q0 + row) * DIM))[chunk];
            *(uint4*)(Bs + row * PITCH + chunk * 8) = vb;
        }
    }
    __syncthreads();

    if (tid == 0) {
        double tl = 0.0;
#pragma unroll
        for (int w = 0; w < 8; w++) tl += sredl[w];
        atomicAdd(&g_acc[0], tl);
    }

    // ===== MMA mainloop: warp -> 32x32 (m_base = (wid&3)*32, n_base = (wid>>2)*32)
    int m_base = (wid & 3) * 32;
    int n_base = (wid >> 2) * 32;

    float acc[2][4][4];
#pragma unroll
    for (int mi = 0; mi < 2; mi++)
#pragma unroll
        for (int nj = 0; nj < 4; nj++)
#pragma unroll
            for (int r = 0; r < 4; r++) acc[mi][nj][r] = 0.f;

    int a_row_off = lane & 15;
    int a_k_off   = 8 * (lane >> 4);
    int b_row_off = ((lane >> 4) << 3) + (lane & 7);
    int b_k_off   = ((lane >> 3) & 1) * 8;

#pragma unroll
    for (int k0 = 0; k0 < DIM; k0 += 16) {
        uint32_t a[2][4];
#pragma unroll
        for (int mi = 0; mi < 2; mi++) {
            const __nv_bfloat16* pa =
                As + (m_base + mi * 16 + a_row_off) * PITCH + k0 + a_k_off;
            ldsm_x4(a[mi][0], a[mi][1], a[mi][2], a[mi][3], pa);
        }
        uint32_t b[4][2];
#pragma unroll
        for (int pr = 0; pr < 2; pr++) {
            const __nv_bfloat16* pb =
                Bs + (n_base + pr * 16 + b_row_off) * PITCH + k0 + b_k_off;
            uint32_t r0, r1, r2, r3;
            ldsm_x4(r0, r1, r2, r3, pb);
            b[pr * 2][0] = r0; b[pr * 2][1] = r1;
            b[pr * 2 + 1][0] = r2; b[pr * 2 + 1][1] = r3;
        }
#pragma unroll
        for (int mi = 0; mi < 2; mi++)
#pragma unroll
            for (int nj = 0; nj < 4; nj++)
                mma16816(acc[mi][nj], a[mi], b[nj]);
    }

    // ===== fused epilogue =====
    int g = lane >> 2, tt = lane & 3;
    float nsv[4], bpsv[4];
#pragma unroll
    for (int mi = 0; mi < 2; mi++) {
        int r = s0 + m_base + mi * 16 + g;
        nsv[2 * mi]      = g_ns[r];      nsv[2 * mi + 1]  = g_ns[r + 8];
        bpsv[2 * mi]     = g_bps[r];     bpsv[2 * mi + 1] = g_bps[r + 8];
    }
    float nqv[8], bpv[8];
#pragma unroll
    for (int nj = 0; nj < 4; nj++) {
        int c = q0 + n_base + nj * 8 + 2 * tt;
        nqv[2 * nj]      = g_nq[c];      nqv[2 * nj + 1] = g_nq[c + 1];
        bpv[2 * nj]      = g_bp[c];      bpv[2 * nj + 1] = g_bp[c + 1];
    }

    float lsum0 = 0.f, lsum1 = 0.f;
    if (!masked) {
#pragma unroll
        for (int mi = 0; mi < 2; mi++) {
#pragma unroll
            for (int nj = 0; nj < 4; nj++) {
#pragma unroll
                for (int rr = 0; rr < 4; rr++) {
                    float ns = nsv[2 * mi + (rr >> 1)];
                    float bs = bpsv[2 * mi + (rr >> 1)];
                    float nq = nqv[2 * nj + (rr & 1)];
                    float bq = bpv[2 * nj + (rr & 1)];
                    float sq = fmaxf(ns + fmaf(-2.f, acc[mi][nj][rr], nq), 0.f);
                    float e  = fex2_ap((bs + bq) - fsqrt_ap(sq));
                    if (rr & 1) lsum1 += e; else lsum0 += e;
                }
            }
        }
    } else {
#pragma unroll
        for (int mi = 0; mi < 2; mi++) {
            int rg0 = s0 + m_base + mi * 16 + g;
#pragma unroll
            for (int nj = 0; nj < 4; nj++) {
                int cg0 = q0 + n_base + nj * 8 + 2 * tt;
#pragma unroll
                for (int rr = 0; rr < 4; rr++) {
                    int rg = rg0 + (rr >> 1) * 8;
                    int cg = cg0 + (rr & 1);
                    float ns = nsv[2 * mi + (rr >> 1)];
                    float bs = bpsv[2 * mi + (rr >> 1)];
                    float nq = nqv[2 * nj + (rr & 1)];
                    float bq = bpv[2 * nj + (rr & 1)];
                    float sq = fmaxf(ns + fmaf(-2.f, acc[mi][nj][rr], nq), 0.f);
                    float e  = fex2_ap((bs + bq) - fsqrt_ap(sq));
                    if (cg > rg) { if (rr & 1) lsum1 += e; else lsum0 += e; }
                }
            }
        }
    }

    float lsum = lsum0 + lsum1;
#pragma unroll
    for (int o = 16; o; o >>= 1) lsum += __shfl_xor_sync(0xffffffffu, lsum, o);
    if (lane == 0) sredn[wid] = (double)lsum;
    __syncthreads();
    if (tid == 0) {
        double s = 0.0;
#pragma unroll
        for (int w = 0; w < 8; w++) s += sredn[w];
        atomicAdd(&g_acc[1], s);
        __threadfence();
        unsigned int done = atomicAdd(&g_done, 1u);
        if (done == NT2 - 1) {
            g_done = 0u;
            out[0] = (float)(g_acc[1] - g_acc[0]);
        }
    }
}

// ---------------- launch --------------------------------------------------------
extern "C" void kernel_launch(void* const* d_in, const int* in_sizes, int n_in,
                              void* d_out, int out_size) {
    const int*   edges        = (const int*)d_in[0];
    const int*   nodes_p_star = (const int*)d_in[1];
    const int*   nodes_p      = (const int*)d_in[2];
    const float* beta_p       = (const float*)d_in[3];
    const float* beta_p_star  = (const float*)d_in[4];
    const float* p            = (const float*)d_in[5];
    const float* p_star       = (const float*)d_in[6];
    float* out = (float*)d_out;

    static const size_t NL_SMEM = (128 + 64) * PITCH * sizeof(__nv_bfloat16); // 52224 B
    cudaFuncSetAttribute(fused_kernel,
                         cudaFuncAttributeMaxDynamicSharedMemorySize, (int)NL_SMEM);

    gather_kernel<<<(2 * BATCH) / 8, 256>>>(nodes_p_star, nodes_p,
                                            beta_p, beta_p_star, p, p_star);

    fused_kernel<<<NT2, 256, NL_SMEM>>>(edges, beta_p, beta_p_star, p, p_star, out);
}

// round 14
// speedup vs baseline: 1.7325x; 1.1557x over previous
#include <cuda_runtime.h>
#include <cuda_bf16.h>
#include <cstdint>

#define BATCH  16384
#define DIM    128
#define NEDGES 500000
#define EPSL   1e-6f
#define PITCH  136   // bf16 elems per smem row (272 B = 17*16B) -> ldmatrix conflict-free
#define NT2    16512 // (128s x 64q) tiles kept
#define L2E    1.4426950408889634f
#define L2E2   (1.4426950408889634f * 1.4426950408889634f)

// ---------------- device scratch ------------------------------------------------
__device__ float          g_ns[BATCH];
__device__ float          g_nq[BATCH];
__device__ float          g_bps[BATCH];
__device__ float          g_bp[BATCH];
__device__ __nv_bfloat16  g_psh[BATCH * DIM];
__device__ __nv_bfloat16  g_pph[BATCH * DIM];
__device__ double         g_acc[2];             // [0]=link, [1]=non_link
__device__ unsigned int   g_done;

// ---------------- gather (+ zero accumulators) ----------------------------------
__global__ void gather_kernel(const int* __restrict__ nodes_p_star,
                              const int* __restrict__ nodes_p,
                              const float* __restrict__ beta_p,
                              const float* __restrict__ beta_p_star,
                              const float* __restrict__ p,
                              const float* __restrict__ p_star) {
    if (blockIdx.x == 0 && threadIdx.x == 0) { g_acc[0] = 0.0; g_acc[1] = 0.0; }
    int gw   = (blockIdx.x * blockDim.x + threadIdx.x) >> 5;
    int lane = threadIdx.x & 31;
    if (gw >= 2 * BATCH) return;
    bool is_ps = (gw < BATCH);
    int r   = is_ps ? gw : gw - BATCH;
    int idx = is_ps ? nodes_p_star[r] : nodes_p[r];
    const float4* src = (const float4*)((is_ps ? p_star : p) + (size_t)idx * DIM);
    __nv_bfloat162* dsth = (__nv_bfloat162*)((is_ps ? g_psh : g_pph) + (size_t)r * DIM);
    float nrm = 0.f;
#pragma unroll
    for (int c = lane; c < DIM / 4; c += 32) {
        float4 v = src[c];
        nrm += v.x * v.x + v.y * v.y + v.z * v.z + v.w * v.w;
        dsth[2 * c]     = __floats2bfloat162_rn(v.x * L2E, v.y * L2E);
        dsth[2 * c + 1] = __floats2bfloat162_rn(v.z * L2E, v.w * L2E);
    }
#pragma unroll
    for (int o = 16; o; o >>= 1) nrm += __shfl_xor_sync(0xffffffffu, nrm, o);
    if (lane == 0) {
        if (is_ps) { g_ns[r] = nrm * L2E2; g_bps[r] = beta_p_star[idx] * L2E; }
        else       { g_nq[r] = nrm * L2E2; g_bp[r]  = beta_p[idx] * L2E; }
    }
}

// ---------------- helpers -------------------------------------------------------
__device__ __forceinline__ void ldsm_x4(uint32_t& r0, uint32_t& r1,
                                        uint32_t& r2, uint32_t& r3, const void* p) {
    uint32_t a = (uint32_t)__cvta_generic_to_shared(p);
    asm volatile("ldmatrix.sync.aligned.m8n8.x4.shared.b16 {%0,%1,%2,%3},[%4];"
                 : "=r"(r0), "=r"(r1), "=r"(r2), "=r"(r3) : "r"(a));
}
__device__ __forceinline__ void mma16816(float* c, const uint32_t* a, const uint32_t* b) {
    asm volatile(
        "mma.sync.aligned.m16n8k16.row.col.f32.bf16.bf16.f32 "
        "{%0,%1,%2,%3},{%4,%5,%6,%7},{%8,%9},{%0,%1,%2,%3};"
        : "+f"(c[0]), "+f"(c[1]), "+f"(c[2]), "+f"(c[3])
        : "r"(a[0]), "r"(a[1]), "r"(a[2]), "r"(a[3]), "r"(b[0]), "r"(b[1]));
}
__device__ __forceinline__ float fsqrt_ap(float x) {
    float r; asm("sqrt.approx.f32 %0, %1;" : "=f"(r) : "f"(x)); return r;
}
__device__ __forceinline__ float fex2_ap(float x) {
    float r; asm("ex2.approx.f32 %0, %1;" : "=f"(r) : "f"(x)); return r;
}
__device__ __forceinline__ void cp16(void* dst_smem, const void* src_gmem) {
    uint32_t d = (uint32_t)__cvta_generic_to_shared(dst_smem);
    asm volatile("cp.async.cg.shared.global [%0], [%1], 16;"
                 :: "r"(d), "l"(src_gmem) : "memory");
}

// ---------------- fused: async fill + link prologue + 128x64 tile ---------------
__global__ void __launch_bounds__(256, 4) fused_kernel(
        const int* __restrict__ edges,
        const float* __restrict__ beta_p,
        const float* __restrict__ beta_p_star,
        const float* __restrict__ p,
        const float* __restrict__ p_star,
        float* __restrict__ out) {
    extern __shared__ __nv_bfloat16 sm[];
    __nv_bfloat16* As = sm;                // [128][PITCH]
    __nv_bfloat16* Bs = sm + 128 * PITCH;  // [64][PITCH]
    __shared__ double sredl[8];
    __shared__ double sredn[8];

    int bid  = blockIdx.x;
    int tid  = threadIdx.x;
    int lane = tid & 31;
    int wid  = tid >> 5;

    // ===== tile decode: cum(ts) = ts*(257-ts), tq2 = 2*ts + off =====
    int t  = bid;
    int ts = (int)((257.f - fsqrt_ap(66049.f - 4.f * (float)t)) * 0.5f);
    while (ts > 0 && ts * (257 - ts) > t) ts--;
    while ((ts + 1) * (257 - (ts + 1)) <= t) ts++;
    int off = t - ts * (257 - ts);
    int tq2 = 2 * ts + off;
    int s0 = ts * 128, q0 = tq2 * 64;
    bool masked = (off < 2);

    // ===== async smem fill (in flight during link prologue) =====
    {
        int chunk = tid & 15;
        int rbase = tid >> 4;
#pragma unroll
        for (int i = 0; i < 8; i++) {
            int row = rbase + 16 * i;
            cp16(As + row * PITCH + chunk * 8,
                 g_psh + (size_t)(s0 + row) * DIM + chunk * 8);
        }
#pragma unroll
        for (int i = 0; i < 4; i++) {
            int row = rbase + 16 * i;
            cp16(Bs + row * PITCH + chunk * 8,
                 g_pph + (size_t)(q0 + row) * DIM + chunk * 8);
        }
        asm volatile("cp.async.commit_group;" ::: "memory");
    }

    // ===== link prologue: grid-strided edges, one warp per edge =====
    {
        float wacc = 0.f;
        for (int e = bid * 8 + wid; e < NEDGES; e += NT2 * 8) {
            int i0 = edges[e];
            int i1 = edges[NEDGES + e];
            float4 av = ((const float4*)(p      + (size_t)i0 * DIM))[lane];
            float4 bv = ((const float4*)(p_star + (size_t)i1 * DIM))[lane];
            float dx = av.x - bv.x + EPSL;
            float dy = av.y - bv.y + EPSL;
            float dz = av.z - bv.z + EPSL;
            float dw = av.w - bv.w + EPSL;
            float s = dx * dx + dy * dy + dz * dz + dw * dw;
#pragma unroll
            for (int o = 16; o; o >>= 1) s += __shfl_xor_sync(0xffffffffu, s, o);
            if (lane == 0)
                wacc += beta_p_star[i0] + beta_p[i1] - fsqrt_ap(s);
        }
        if (lane == 0) sredl[wid] = (double)wacc;
    }

    asm volatile("cp.async.wait_group 0;" ::: "memory");
    __syncthreads();

    if (tid == 0) {
        double tl = 0.0;
#pragma unroll
        for (int w = 0; w < 8; w++) tl += sredl[w];
        atomicAdd(&g_acc[0], tl);
    }

    // ===== MMA mainloop: warp -> 32x32 (m_base = (wid&3)*32, n_base = (wid>>2)*32)
    int m_base = (wid & 3) * 32;
    int n_base = (wid >> 2) * 32;

    float acc[2][4][4];
#pragma unroll
    for (int mi = 0; mi < 2; mi++)
#pragma unroll
        for (int nj = 0; nj < 4; nj++)
#pragma unroll
            for (int r = 0; r < 4; r++) acc[mi][nj][r] = 0.f;

    int a_row_off = lane & 15;
    int a_k_off   = 8 * (lane >> 4);
    int b_row_off = ((lane >> 4) << 3) + (lane & 7);
    int b_k_off   = ((lane >> 3) & 1) * 8;

#pragma unroll
    for (int k0 = 0; k0 < DIM; k0 += 16) {
        uint32_t a[2][4];
#pragma unroll
        for (int mi = 0; mi < 2; mi++) {
            const __nv_bfloat16* pa =
                As + (m_base + mi * 16 + a_row_off) * PITCH + k0 + a_k_off;
            ldsm_x4(a[mi][0], a[mi][1], a[mi][2], a[mi][3], pa);
        }
        uint32_t b[4][2];
#pragma unroll
        for (int pr = 0; pr < 2; pr++) {
            const __nv_bfloat16* pb =
                Bs + (n_base + pr * 16 + b_row_off) * PITCH + k0 + b_k_off;
            uint32_t r0, r1, r2, r3;
            ldsm_x4(r0, r1, r2, r3, pb);
            b[pr * 2][0] = r0; b[pr * 2][1] = r1;
            b[pr * 2 + 1][0] = r2; b[pr * 2 + 1][1] = r3;
        }
#pragma unroll
        for (int mi = 0; mi < 2; mi++)
#pragma unroll
            for (int nj = 0; nj < 4; nj++)
                mma16816(acc[mi][nj], a[mi], b[nj]);
    }

    // ===== fused epilogue (ex2-folded, approx MUFU) =====
    int g = lane >> 2, tt = lane & 3;
    float nsv[4], bpsv[4];
#pragma unroll
    for (int mi = 0; mi < 2; mi++) {
        int r = s0 + m_base + mi * 16 + g;
        nsv[2 * mi]      = g_ns[r];      nsv[2 * mi + 1]  = g_ns[r + 8];
        bpsv[2 * mi]     = g_bps[r];     bpsv[2 * mi + 1] = g_bps[r + 8];
    }
    float nqv[8], bpv[8];
#pragma unroll
    for (int nj = 0; nj < 4; nj++) {
        int c = q0 + n_base + nj * 8 + 2 * tt;
        nqv[2 * nj]      = g_nq[c];      nqv[2 * nj + 1] = g_nq[c + 1];
        bpv[2 * nj]      = g_bp[c];      bpv[2 * nj + 1] = g_bp[c + 1];
    }

    float lsum0 = 0.f, lsum1 = 0.f;
    if (!masked) {
#pragma unroll
        for (int mi = 0; mi < 2; mi++) {
#pragma unroll
            for (int nj = 0; nj < 4; nj++) {
#pragma unroll
                for (int rr = 0; rr < 4; rr++) {
                    float ns = nsv[2 * mi + (rr >> 1)];
                    float bs = bpsv[2 * mi + (rr >> 1)];
                    float nq = nqv[2 * nj + (rr & 1)];
                    float bq = bpv[2 * nj + (rr & 1)];
                    float sq = fmaxf(ns + fmaf(-2.f, acc[mi][nj][rr], nq), 0.f);
                    float e  = fex2_ap((bs + bq) - fsqrt_ap(sq));
                    if (rr & 1) lsum1 += e; else lsum0 += e;
                }
            }
        }
    } else {
#pragma unroll
        for (int mi = 0; mi < 2; mi++) {
            int rg0 = s0 + m_base + mi * 16 + g;
#pragma unroll
            for (int nj = 0; nj < 4; nj++) {
                int cg0 = q0 + n_base + nj * 8 + 2 * tt;
#pragma unroll
                for (int rr = 0; rr < 4; rr++) {
                    int rg = rg0 + (rr >> 1) * 8;
                    int cg = cg0 + (rr & 1);
                    float ns = nsv[2 * mi + (rr >> 1)];
                    float bs = bpsv[2 * mi + (rr >> 1)];
                    float nq = nqv[2 * nj + (rr & 1)];
                    float bq = bpv[2 * nj + (rr & 1)];
                    float sq = fmaxf(ns + fmaf(-2.f, acc[mi][nj][rr], nq), 0.f);
                    float e  = fex2_ap((bs + bq) - fsqrt_ap(sq));
                    if (cg > rg) { if (rr & 1) lsum1 += e; else lsum0 += e; }
                }
            }
        }
    }

    float lsum = lsum0 + lsum1;
#pragma unroll
    for (int o = 16; o; o >>= 1) lsum += __shfl_xor_sync(0xffffffffu, lsum, o);
    if (lane == 0) sredn[wid] = (double)lsum;
    __syncthreads();
    if (tid == 0) {
        double s = 0.0;
#pragma unroll
        for (int w = 0; w < 8; w++) s += sredn[w];
        atomicAdd(&g_acc[1], s);
        __threadfence();
        unsigned int done = atomicAdd(&g_done, 1u);
        if (done == NT2 - 1) {
            g_done = 0u;
            out[0] = (float)(g_acc[1] - g_acc[0]);
        }
    }
}

// ---------------- launch --------------------------------------------------------
extern "C" void kernel_launch(void* const* d_in, const int* in_sizes, int n_in,
                              void* d_out, int out_size) {
    const int*   edges        = (const int*)d_in[0];
    const int*   nodes_p_star = (const int*)d_in[1];
    const int*   nodes_p      = (const int*)d_in[2];
    const float* beta_p       = (const float*)d_in[3];
    const float* beta_p_star  = (const float*)d_in[4];
    const float* p            = (const float*)d_in[5];
    const float* p_star       = (const float*)d_in[6];
    float* out = (float*)d_out;

    static const size_t NL_SMEM = (128 + 64) * PITCH * sizeof(__nv_bfloat16); // 52224 B
    cudaFuncSetAttribute(fused_kernel,
                         cudaFuncAttributeMaxDynamicSharedMemorySize, (int)NL_SMEM);

    gather_kernel<<<(2 * BATCH) / 8, 256>>>(nodes_p_star, nodes_p,
                                            beta_p, beta_p_star, p, p_star);

    fused_kernel<<<NT2, 256, NL_SMEM>>>(edges, beta_p, beta_p_star, p, p_star, out);
}